// round 6
// baseline (speedup 1.0000x reference)
#include <cuda_runtime.h>

#define N_PROP 65536
#define N_TGT  128
#define KTOP   8
#define NPB    32   // proposals per block in the score kernel

typedef unsigned long long u64;

// Scratch (static __device__ — no allocations allowed)
__device__ float g_scoresT[(size_t)N_TGT * N_PROP];   // [T][N] logit keys
__device__ float g_top_val[N_TGT * KTOP];
__device__ int   g_top_idx[N_TGT * KTOP];

// ---- packed f32x2 helpers (sm_100+ FFMA2 path; per-lane IEEE fp32) --------
__device__ __forceinline__ u64 fma2(u64 a, u64 b, u64 c) {
    u64 d;
    asm("fma.rn.f32x2 %0, %1, %2, %3;" : "=l"(d) : "l"(a), "l"(b), "l"(c));
    return d;
}
__device__ __forceinline__ u64 pack2(float lo, float hi) {
    u64 d; asm("mov.b64 %0, {%1, %2};" : "=l"(d) : "f"(lo), "f"(hi)); return d;
}
__device__ __forceinline__ void unpack2(u64 x, float& lo, float& hi) {
    asm("mov.b64 {%0, %1}, %2;" : "=f"(lo), "=f"(hi) : "l"(x));
}
__device__ __forceinline__ u64 relu2(u64 x) {
    float lo, hi; unpack2(x, lo, hi);
    return pack2(fmaxf(lo, 0.0f), fmaxf(hi, 0.0f));
}

// ---------------------------------------------------------------------------
// Kernel 1: MLP scoring. blockDim=128 (thread = target t), block covers NPB
// proposals, 2 per iteration.
//  - Layer 1: f32x2 lanes = (proposal a, proposal b); W1 duplicated pairs (4KB).
//  - Layer 2/3: f32x2 lanes = (j, j+1) output pairs; W2/W3 plain consecutive
//    bit-packs (no duplication), hidden activation splatted from registers.
// __launch_bounds__(128, 4): cap regs at 128 -> 4 blocks/SM (16 warps) to
// cover LDS/dependency latency (R5 showed issue=55% with only 3 warps/SMSP).
// key = logit if logit >= 0 else -1.0 (sigmoid monotone; sentinel reproduces
// the thresholded-zeros tie of the reference exactly).
// ---------------------------------------------------------------------------
__global__ __launch_bounds__(128, 4) void score_kernel(
    const float* __restrict__ th, const float* __restrict__ xy,
    const float* __restrict__ di, const float* __restrict__ po,
    const float* __restrict__ ne, const float* __restrict__ io,
    const float* __restrict__ W1, const float* __restrict__ b1,
    const float* __restrict__ W2, const float* __restrict__ b2,
    const float* __restrict__ W3, const float* __restrict__ b3)
{
    __shared__ __align__(16) u64 sW1p[64 * 8];   // dup pairs [i][k0..k5,bias,pad] 4KB
    __shared__ __align__(16) u64 sW2j[64 * 16];  // [i][j8] = (W2[i][2j8],W2[i][2j8+1]) 8KB
    __shared__ __align__(16) u64 sW3j[16];       // (W3[2j],W3[2j+1])
    __shared__ __align__(16) u64 sB2j[16];       // (b2[2j],b2[2j+1])
    __shared__ float sB3;

    const int tid = threadIdx.x;

    for (int x = tid; x < 64 * 8; x += 128) {
        int i = x >> 3, k = x & 7;
        float v = 0.0f;
        if (k < 6)       v = W1[k * 64 + i];
        else if (k == 6) v = b1[i];
        sW1p[x] = pack2(v, v);
    }
    for (int x = tid; x < 64 * 16; x += 128) {
        sW2j[x] = pack2(W2[2 * x], W2[2 * x + 1]);   // row-major consecutive
    }
    if (tid < 16) {
        sW3j[tid] = pack2(W3[2 * tid], W3[2 * tid + 1]);
        sB2j[tid] = pack2(b2[2 * tid], b2[2 * tid + 1]);
    }
    if (tid == 0) sB3 = b3[0];
    __syncthreads();

    const int t  = tid;            // target index 0..127
    const int n0 = blockIdx.x * NPB;

    for (int nn = 0; nn < NPB; nn += 2) {
        const int na = n0 + nn;
        const int oa = na * N_TGT + t;
        const int ob = oa + N_TGT;

        u64 pf[6];
        {
            float fa0 = 1.0f - fminf(th[oa], 180.0f) * (1.0f / 180.0f);
            float fb0 = 1.0f - fminf(th[ob], 180.0f) * (1.0f / 180.0f);
            float fa1 = 1.0f - fminf(xy[oa], 800.0f) * (1.0f / 800.0f);
            float fb1 = 1.0f - fminf(xy[ob], 800.0f) * (1.0f / 800.0f);
            float fa2 = 1.0f - fminf(di[oa], 800.0f) * (1.0f / 800.0f);
            float fb2 = 1.0f - fminf(di[ob], 800.0f) * (1.0f / 800.0f);
            pf[0] = pack2(fa0, fb0);
            pf[1] = pack2(fa1, fb1);
            pf[2] = pack2(fa2, fb2);
            pf[3] = pack2(po[oa], po[ob]);
            pf[4] = pack2(ne[oa], ne[ob]);
            pf[5] = pack2(io[oa], io[ob]);
        }

        u64 h2a[16], h2b[16];
        #pragma unroll
        for (int j = 0; j < 16; j++) { h2a[j] = sB2j[j]; h2b[j] = sB2j[j]; }

        #pragma unroll 2
        for (int i = 0; i < 64; i++) {
            // Layer 1: proposal-packed (needs duplicated W1 pairs)
            const ulonglong2 q0 = ((const ulonglong2*)sW1p)[i * 4 + 0]; // k0,k1
            const ulonglong2 q1 = ((const ulonglong2*)sW1p)[i * 4 + 1]; // k2,k3
            const ulonglong2 q2 = ((const ulonglong2*)sW1p)[i * 4 + 2]; // k4,k5
            u64 h = sW1p[i * 8 + 6];                                    // bias pair

            h = fma2(pf[0], q0.x, h);
            h = fma2(pf[1], q0.y, h);
            h = fma2(pf[2], q1.x, h);
            h = fma2(pf[3], q1.y, h);
            h = fma2(pf[4], q2.x, h);
            h = fma2(pf[5], q2.y, h);

            float hlo, hhi;
            unpack2(h, hlo, hhi);
            const u64 hap = pack2(fmaxf(hlo, 0.0f), fmaxf(hlo, 0.0f)); // (ha,ha)
            const u64 hbp = pack2(fmaxf(hhi, 0.0f), fmaxf(hhi, 0.0f)); // (hb,hb)

            // Layer 2: j-packed; one W2 row read feeds both proposals
            const ulonglong2* w2row = (const ulonglong2*)&sW2j[i * 16];
            #pragma unroll
            for (int q = 0; q < 8; q++) {
                const ulonglong2 w = w2row[q];
                h2a[2 * q + 0] = fma2(hap, w.x, h2a[2 * q + 0]);
                h2a[2 * q + 1] = fma2(hap, w.y, h2a[2 * q + 1]);
                h2b[2 * q + 0] = fma2(hbp, w.x, h2b[2 * q + 0]);
                h2b[2 * q + 1] = fma2(hbp, w.y, h2b[2 * q + 1]);
            }
        }

        // Layer 3: j-packed relu+dot, then horizontal add
        u64 acpa = 0, acpb = 0;   // bit pattern (0.0f,0.0f)
        #pragma unroll
        for (int j = 0; j < 16; j++) {
            const u64 w = sW3j[j];
            acpa = fma2(relu2(h2a[j]), w, acpa);
            acpb = fma2(relu2(h2b[j]), w, acpb);
        }
        float a0, a1, b0v, b1v;
        unpack2(acpa, a0, a1);
        unpack2(acpb, b0v, b1v);
        const float acca = sB3 + a0 + a1;
        const float accb = sB3 + b0v + b1v;

        float2 keys;
        keys.x = (acca >= 0.0f) ? acca : -1.0f;
        keys.y = (accb >= 0.0f) ? accb : -1.0f;
        *(float2*)&g_scoresT[(size_t)t * N_PROP + na] = keys;
    }
}

// ---------------------------------------------------------------------------
// Kernel 2: per-target top-8, ties broken by lowest index (lax.top_k rule).
// 512 threads/block; float4 loads; strict > keeps earliest index on ties.
// ---------------------------------------------------------------------------
__global__ __launch_bounds__(512) void topk_kernel()
{
    __shared__ float sval[512 * KTOP];
    __shared__ int   sidx[512 * KTOP];

    const int t   = blockIdx.x;
    const int tid = threadIdx.x;
    const float4* __restrict__ col4 = (const float4*)(g_scoresT + (size_t)t * N_PROP);

    float val[KTOP];
    int   idx[KTOP];
    #pragma unroll
    for (int k = 0; k < KTOP; k++) { val[k] = -3.4e38f; idx[k] = 0x7fffffff; }

    for (int q = tid; q < N_PROP / 4; q += 512) {
        const float4 v4 = col4[q];
        const int nb = q * 4;
        float vv[4] = {v4.x, v4.y, v4.z, v4.w};
        #pragma unroll
        for (int u = 0; u < 4; u++) {
            const float v = vv[u];
            if (v > val[KTOP - 1]) {
                val[KTOP - 1] = v; idx[KTOP - 1] = nb + u;
                #pragma unroll
                for (int p = KTOP - 1; p > 0; p--) {
                    if (val[p] > val[p - 1]) {
                        float tv = val[p]; val[p] = val[p - 1]; val[p - 1] = tv;
                        int   ti = idx[p]; idx[p] = idx[p - 1]; idx[p - 1] = ti;
                    }
                }
            }
        }
    }

    #pragma unroll
    for (int k = 0; k < KTOP; k++) { sval[tid * KTOP + k] = val[k]; sidx[tid * KTOP + k] = idx[k]; }
    __syncthreads();

    for (int s = 256; s > 0; s >>= 1) {
        float mv[KTOP]; int mi[KTOP];
        if (tid < s) {
            const float* av = &sval[tid * KTOP];
            const int*   ai = &sidx[tid * KTOP];
            const float* bv = &sval[(tid + s) * KTOP];
            const int*   bi = &sidx[(tid + s) * KTOP];
            int i = 0, j = 0;
            #pragma unroll
            for (int k = 0; k < KTOP; k++) {
                const float va = av[i], vb = bv[j];
                const int   ia = ai[i], ib = bi[j];
                const bool take_a = (va > vb) || (va == vb && ia < ib);
                if (take_a) { mv[k] = va; mi[k] = ia; i++; }
                else        { mv[k] = vb; mi[k] = ib; j++; }
            }
            #pragma unroll
            for (int k = 0; k < KTOP; k++) { sval[tid * KTOP + k] = mv[k]; sidx[tid * KTOP + k] = mi[k]; }
        }
        __syncthreads();
    }

    if (tid == 0) {
        #pragma unroll
        for (int k = 0; k < KTOP; k++) {
            g_top_val[t * KTOP + k] = sval[k];
            g_top_idx[t * KTOP + k] = sidx[k];
        }
    }
}

// ---------------------------------------------------------------------------
// Kernel 3: stable descending rank of targets[:,1], scatter output as float32.
// out = [rows(1024) | cols(1024) | valid(1024)].
// ---------------------------------------------------------------------------
__global__ __launch_bounds__(N_TGT) void assemble_kernel(
    const float* __restrict__ targets, float* __restrict__ out)
{
    __shared__ float key[N_TGT];
    const int t = threadIdx.x;
    key[t] = targets[t * 4 + 1];
    __syncthreads();

    const float kt = key[t];
    int r = 0;
    #pragma unroll 8
    for (int j = 0; j < N_TGT; j++) {
        const float kj = key[j];
        r += (kj > kt) || (kj == kt && j < t);   // stable descending
    }

    #pragma unroll
    for (int k = 0; k < KTOP; k++) {
        const int src = t * KTOP + k;
        const int dst = r * KTOP + k;
        out[dst]        = (float)g_top_idx[src];                  // rows
        out[1024 + dst] = (float)t;                               // cols
        out[2048 + dst] = (g_top_val[src] >= 0.0f) ? 1.0f : 0.0f; // valid
    }
}

// ---------------------------------------------------------------------------
extern "C" void kernel_launch(void* const* d_in, const int* in_sizes, int n_in,
                              void* d_out, int out_size)
{
    const float *th, *xy, *di, *po, *ne, *io, *tg, *W1, *b1, *W2, *b2, *W3, *b3;

    if (n_in >= 13 && in_sizes[0] == 6 * 64) {
        // Alphabetical metadata order
        W1 = (const float*)d_in[0];  W2 = (const float*)d_in[1];
        W3 = (const float*)d_in[2];  b1 = (const float*)d_in[3];
        b2 = (const float*)d_in[4];  b3 = (const float*)d_in[5];
        di = (const float*)d_in[6];  io = (const float*)d_in[7];
        ne = (const float*)d_in[8];  po = (const float*)d_in[9];
        xy = (const float*)d_in[10]; tg = (const float*)d_in[11];
        th = (const float*)d_in[12];
    } else {
        // Insertion (dict) order
        th = (const float*)d_in[0];  xy = (const float*)d_in[1];
        di = (const float*)d_in[2];  po = (const float*)d_in[3];
        ne = (const float*)d_in[4];  io = (const float*)d_in[5];
        tg = (const float*)d_in[6];  W1 = (const float*)d_in[7];
        b1 = (const float*)d_in[8];  W2 = (const float*)d_in[9];
        b2 = (const float*)d_in[10]; W3 = (const float*)d_in[11];
        b3 = (const float*)d_in[12];
    }

    score_kernel<<<N_PROP / NPB, 128>>>(th, xy, di, po, ne, io,
                                        W1, b1, W2, b2, W3, b3);
    topk_kernel<<<N_TGT, 512>>>();
    assemble_kernel<<<1, N_TGT>>>(tg, (float*)d_out);
}

// round 13
// speedup vs baseline: 3.2456x; 3.2456x over previous
#include <cuda_runtime.h>
#include <cuda_bf16.h>

#define N_PROP 65536
#define N_TGT  128
#define KTOP   8
#define KCAND  16

typedef unsigned int u32;

// Scratch (static __device__ — no allocations allowed)
__device__ float g_scoresT[(size_t)N_TGT * N_PROP];   // [T][N] approx keys
__device__ int   g_cand_idx[N_TGT * KCAND];
__device__ float g_top_val[N_TGT * KTOP];
__device__ int   g_top_idx[N_TGT * KTOP];

// pack two f32 -> bf16x2 (lo = second arg)
static __device__ __forceinline__ u32 bfpair(float hi, float lo) {
    u32 d;
    asm("cvt.rn.bf16x2.f32 %0, %1, %2;" : "=r"(d) : "f"(hi), "f"(lo));
    return d;
}

static __device__ __forceinline__ void mma_k8(float c[4], u32 a0, u32 a1, u32 b0) {
    asm volatile(
        "mma.sync.aligned.m16n8k8.row.col.f32.bf16.bf16.f32 "
        "{%0,%1,%2,%3}, {%4,%5}, {%6}, {%0,%1,%2,%3};"
        : "+f"(c[0]), "+f"(c[1]), "+f"(c[2]), "+f"(c[3])
        : "r"(a0), "r"(a1), "r"(b0));
}
static __device__ __forceinline__ void mma_k16(float c[4], u32 a0, u32 a1, u32 a2, u32 a3,
                                               u32 b0, u32 b1) {
    asm volatile(
        "mma.sync.aligned.m16n8k16.row.col.f32.bf16.bf16.f32 "
        "{%0,%1,%2,%3}, {%4,%5,%6,%7}, {%8,%9}, {%0,%1,%2,%3};"
        : "+f"(c[0]), "+f"(c[1]), "+f"(c[2]), "+f"(c[3])
        : "r"(a0), "r"(a1), "r"(a2), "r"(a3), "r"(b0), "r"(b1));
}

// ---------------------------------------------------------------------------
// Phase A: warp-level HMMA approximate scoring. Rows = (n,t) pairs,
// row = n*128 + t (the flat index of the six [N,T] arrays). Per warp-tile
// of 16 rows:
//   L1: H1[16,64] = [feats|1][16,8] @ [W1|b1]  -> 8x mma.m16n8k8 (bf16)
//   L2: H2[16,32] = relu(H1) @ W2              -> 16x mma.m16n8k16
//       (L1 C-frags convert to L2 A-frags purely in registers)
//   L3: logit = relu(H2 + b2) . W3 + b3        -> scalar + 2 quad shuffles
// key = logit>=0 ? logit : -1  (approx; exact re-ranking in phase B)
// ---------------------------------------------------------------------------
__global__ __launch_bounds__(128) void score_mma_kernel(
    const float* __restrict__ th, const float* __restrict__ xy,
    const float* __restrict__ di, const float* __restrict__ po,
    const float* __restrict__ ne, const float* __restrict__ io,
    const float* __restrict__ W1, const float* __restrict__ b1,
    const float* __restrict__ W2, const float* __restrict__ b2,
    const float* __restrict__ W3, const float* __restrict__ b3)
{
    const int lane = threadIdx.x & 31;
    const int grp  = lane >> 2;       // 0..7  (row within tile; +8 for upper)
    const int qid  = lane & 3;        // 0..3  (K/N column group)

    const int warps_per_blk = blockDim.x >> 5;
    const int gwarp  = blockIdx.x * warps_per_blk + (threadIdx.x >> 5);
    const int nwarp  = gridDim.x * warps_per_blk;
    const int ntiles = (N_PROP * N_TGT) / 16;

    // ---- W1 B-fragments (k8): b[jt] covers hidden units 8*jt..8*jt+7 ----
    // B[k][n'] with k = feature row (6 = b1 bias row, 7 = 0), n' = grp.
    u32 bw1[8];
    {
        const int k0 = 2 * qid;
        #pragma unroll
        for (int jt = 0; jt < 8; jt++) {
            const int n = 8 * jt + grp;
            float lo = (k0 == 6) ? b1[n] : W1[k0 * 64 + n];
            float hi = (k0 + 1 == 7) ? 0.0f : W1[(k0 + 1) * 64 + n];
            bw1[jt] = bfpair(hi, lo);
        }
    }

    // ---- W2 B-fragments (k16): [kt][nt], kt = K-step (16 H1 units), nt = 8 H2 units
    u32 bw2[4][4][2];
    {
        #pragma unroll
        for (int kt = 0; kt < 4; kt++) {
            const int k0 = 16 * kt + 2 * qid;
            #pragma unroll
            for (int nt = 0; nt < 4; nt++) {
                const int n = 8 * nt + grp;
                bw2[kt][nt][0] = bfpair(W2[(k0 + 1) * 32 + n], W2[k0 * 32 + n]);
                bw2[kt][nt][1] = bfpair(W2[(k0 + 9) * 32 + n], W2[(k0 + 8) * 32 + n]);
            }
        }
    }

    // ---- L3 per-lane constants: cols 8*nt + 2*qid + e ----
    float w3v[4][2], b2v[4][2];
    #pragma unroll
    for (int nt = 0; nt < 4; nt++) {
        #pragma unroll
        for (int e = 0; e < 2; e++) {
            const int c = 8 * nt + 2 * qid + e;
            w3v[nt][e] = W3[c];
            b2v[nt][e] = b2[c];
        }
    }
    const float b3v = b3[0];

    // per-lane feature sources: features 2*qid and 2*qid+1
    const float* pA = (qid == 0) ? th : (qid == 1) ? di : ne;   // qid3: dummy
    const float* pB = (qid == 0) ? xy : (qid == 1) ? po : io;
    const float capA = (qid == 0) ? 180.0f : (qid == 1) ? 800.0f : 0.0f;
    const float capB = (qid == 0) ? 800.0f : 0.0f;
    const float invA = (qid == 0) ? (1.0f / 180.0f) : (1.0f / 800.0f);
    const float invB = 1.0f / 800.0f;

    for (int tile = gwarp; tile < ntiles; tile += nwarp) {
        const int row0 = tile * 16 + grp;     // rows row0 and row0+8

        // ---- A-fragments for L1 (k8): cols 2*qid, 2*qid+1 ----
        u32 a0, a1;
        if (qid == 3) {
            a0 = 0x00003F80u;                 // (col6=1.0 bias, col7=0)
            a1 = 0x00003F80u;
        } else {
            float vA0 = pA[row0],     vB0 = pB[row0];
            float vA8 = pA[row0 + 8], vB8 = pB[row0 + 8];
            float fA0 = (capA > 0.0f) ? 1.0f - fminf(vA0, capA) * invA : vA0;
            float fA8 = (capA > 0.0f) ? 1.0f - fminf(vA8, capA) * invA : vA8;
            float fB0 = (capB > 0.0f) ? 1.0f - fminf(vB0, capB) * invB : vB0;
            float fB8 = (capB > 0.0f) ? 1.0f - fminf(vB8, capB) * invB : vB8;
            a0 = bfpair(fB0, fA0);
            a1 = bfpair(fB8, fA8);
        }

        // ---- L1: 8 N-tiles ----
        float h1[8][4];
        #pragma unroll
        for (int jt = 0; jt < 8; jt++) {
            h1[jt][0] = 0.0f; h1[jt][1] = 0.0f; h1[jt][2] = 0.0f; h1[jt][3] = 0.0f;
            mma_k8(h1[jt], a0, a1, bw1[jt]);
        }

        // ---- L2: relu(H1) in registers -> A-frags; 4 K-steps x 4 N-tiles ----
        float h2[4][4];
        #pragma unroll
        for (int nt = 0; nt < 4; nt++) {
            h2[nt][0] = 0.0f; h2[nt][1] = 0.0f; h2[nt][2] = 0.0f; h2[nt][3] = 0.0f;
        }
        #pragma unroll
        for (int kt = 0; kt < 4; kt++) {
            const u32 A0 = bfpair(fmaxf(h1[2 * kt][1], 0.0f),     fmaxf(h1[2 * kt][0], 0.0f));
            const u32 A1 = bfpair(fmaxf(h1[2 * kt][3], 0.0f),     fmaxf(h1[2 * kt][2], 0.0f));
            const u32 A2 = bfpair(fmaxf(h1[2 * kt + 1][1], 0.0f), fmaxf(h1[2 * kt + 1][0], 0.0f));
            const u32 A3 = bfpair(fmaxf(h1[2 * kt + 1][3], 0.0f), fmaxf(h1[2 * kt + 1][2], 0.0f));
            #pragma unroll
            for (int nt = 0; nt < 4; nt++)
                mma_k16(h2[nt], A0, A1, A2, A3, bw2[kt][nt][0], bw2[kt][nt][1]);
        }

        // ---- L3: relu(H2 + b2) . W3, quad reduction ----
        float p0 = 0.0f, p8 = 0.0f;
        #pragma unroll
        for (int nt = 0; nt < 4; nt++) {
            #pragma unroll
            for (int e = 0; e < 2; e++) {
                p0 = fmaf(fmaxf(h2[nt][e] + b2v[nt][e], 0.0f),     w3v[nt][e], p0);
                p8 = fmaf(fmaxf(h2[nt][2 + e] + b2v[nt][e], 0.0f), w3v[nt][e], p8);
            }
        }
        p0 += __shfl_xor_sync(0xFFFFFFFFu, p0, 1);
        p0 += __shfl_xor_sync(0xFFFFFFFFu, p0, 2);
        p8 += __shfl_xor_sync(0xFFFFFFFFu, p8, 1);
        p8 += __shfl_xor_sync(0xFFFFFFFFu, p8, 2);

        if (qid == 0) {
            const float l0 = p0 + b3v;
            const float l8 = p8 + b3v;
            const float k0 = (l0 >= 0.0f) ? l0 : -1.0f;
            const float k8 = (l8 >= 0.0f) ? l8 : -1.0f;
            const int r0 = row0, r8 = row0 + 8;
            g_scoresT[(size_t)(r0 & 127) * N_PROP + (r0 >> 7)] = k0;
            g_scoresT[(size_t)(r8 & 127) * N_PROP + (r8 >> 7)] = k8;
        }
    }
}

// ---------------------------------------------------------------------------
// Phase A topk: per-target top-16 candidates (ties -> lowest index).
// ---------------------------------------------------------------------------
__global__ __launch_bounds__(256) void topk16_kernel()
{
    __shared__ float sval[256 * KCAND];
    __shared__ int   sidx[256 * KCAND];

    const int t   = blockIdx.x;
    const int tid = threadIdx.x;
    const float4* __restrict__ col4 = (const float4*)(g_scoresT + (size_t)t * N_PROP);

    float val[KCAND];
    int   idx[KCAND];
    #pragma unroll
    for (int k = 0; k < KCAND; k++) { val[k] = -3.4e38f; idx[k] = 0x7fffffff; }

    for (int q = tid; q < N_PROP / 4; q += 256) {
        const float4 v4 = col4[q];
        const int nb = q * 4;
        float vv[4] = {v4.x, v4.y, v4.z, v4.w};
        #pragma unroll
        for (int u = 0; u < 4; u++) {
            const float v = vv[u];
            if (v > val[KCAND - 1]) {
                val[KCAND - 1] = v; idx[KCAND - 1] = nb + u;
                #pragma unroll
                for (int p = KCAND - 1; p > 0; p--) {
                    if (val[p] > val[p - 1]) {
                        float tv = val[p]; val[p] = val[p - 1]; val[p - 1] = tv;
                        int   ti = idx[p]; idx[p] = idx[p - 1]; idx[p - 1] = ti;
                    }
                }
            }
        }
    }

    #pragma unroll
    for (int k = 0; k < KCAND; k++) { sval[tid * KCAND + k] = val[k]; sidx[tid * KCAND + k] = idx[k]; }
    __syncthreads();

    for (int s = 128; s > 0; s >>= 1) {
        float mv[KCAND]; int mi[KCAND];
        if (tid < s) {
            const float* av = &sval[tid * KCAND];
            const int*   ai = &sidx[tid * KCAND];
            const float* bv = &sval[(tid + s) * KCAND];
            const int*   bi = &sidx[(tid + s) * KCAND];
            int i = 0, j = 0;
            #pragma unroll
            for (int k = 0; k < KCAND; k++) {
                const float va = av[i], vb = bv[j];
                const int   ia = ai[i], ib = bi[j];
                const bool take_a = (va > vb) || (va == vb && ia < ib);
                if (take_a) { mv[k] = va; mi[k] = ia; i++; }
                else        { mv[k] = vb; mi[k] = ib; j++; }
            }
            #pragma unroll
            for (int k = 0; k < KCAND; k++) { sval[tid * KCAND + k] = mv[k]; sidx[tid * KCAND + k] = mi[k]; }
        }
        __syncthreads();
    }

    if (tid == 0) {
        #pragma unroll
        for (int k = 0; k < KCAND; k++)
            g_cand_idx[t * KCAND + k] = sidx[k];
    }
}

// ---------------------------------------------------------------------------
// Phase B: exact fp32 rescoring of the 16 candidates per target, exact top-8.
// ---------------------------------------------------------------------------
__global__ __launch_bounds__(32) void rescore_kernel(
    const float* __restrict__ th, const float* __restrict__ xy,
    const float* __restrict__ di, const float* __restrict__ po,
    const float* __restrict__ ne, const float* __restrict__ io,
    const float* __restrict__ W1, const float* __restrict__ b1,
    const float* __restrict__ W2, const float* __restrict__ b2,
    const float* __restrict__ W3, const float* __restrict__ b3)
{
    __shared__ float skv[KCAND];
    __shared__ int   ski[KCAND];

    const int t   = blockIdx.x;
    const int tid = threadIdx.x;

    if (tid < KCAND) {
        const int n   = g_cand_idx[t * KCAND + tid];
        const int off = n * N_TGT + t;
        float f[6];
        f[0] = 1.0f - fminf(th[off], 180.0f) * (1.0f / 180.0f);
        f[1] = 1.0f - fminf(xy[off], 800.0f) * (1.0f / 800.0f);
        f[2] = 1.0f - fminf(di[off], 800.0f) * (1.0f / 800.0f);
        f[3] = po[off];
        f[4] = ne[off];
        f[5] = io[off];

        float h2[32];
        #pragma unroll
        for (int j = 0; j < 32; j++) h2[j] = b2[j];

        for (int i = 0; i < 64; i++) {
            float h = b1[i];
            #pragma unroll
            for (int k = 0; k < 6; k++) h = fmaf(f[k], W1[k * 64 + i], h);
            h = fmaxf(h, 0.0f);
            #pragma unroll
            for (int j = 0; j < 32; j++) h2[j] = fmaf(h, W2[i * 32 + j], h2[j]);
        }
        float acc = b3[0];
        #pragma unroll
        for (int j = 0; j < 32; j++)
            acc = fmaf(fmaxf(h2[j], 0.0f), W3[j], acc);

        skv[tid] = (acc >= 0.0f) ? acc : -1.0f;
        ski[tid] = n;
    }
    __syncthreads();

    if (tid == 0) {
        bool used[KCAND];
        #pragma unroll
        for (int k = 0; k < KCAND; k++) used[k] = false;
        for (int k = 0; k < KTOP; k++) {
            int best = -1;
            float bv = -3.4e38f; int bi = 0x7fffffff;
            for (int c = 0; c < KCAND; c++) {
                if (used[c]) continue;
                const float v = skv[c]; const int n = ski[c];
                if (v > bv || (v == bv && n < bi)) { bv = v; bi = n; best = c; }
            }
            used[best] = true;
            g_top_val[t * KTOP + k] = bv;
            g_top_idx[t * KTOP + k] = bi;
        }
    }
}

// ---------------------------------------------------------------------------
// Final: stable descending rank of targets[:,1], scatter output as float32.
// out = [rows(1024) | cols(1024) | valid(1024)].
// ---------------------------------------------------------------------------
__global__ __launch_bounds__(N_TGT) void assemble_kernel(
    const float* __restrict__ targets, float* __restrict__ out)
{
    __shared__ float key[N_TGT];
    const int t = threadIdx.x;
    key[t] = targets[t * 4 + 1];
    __syncthreads();

    const float kt = key[t];
    int r = 0;
    #pragma unroll 8
    for (int j = 0; j < N_TGT; j++) {
        const float kj = key[j];
        r += (kj > kt) || (kj == kt && j < t);   // stable descending
    }

    #pragma unroll
    for (int k = 0; k < KTOP; k++) {
        const int src = t * KTOP + k;
        const int dst = r * KTOP + k;
        out[dst]        = (float)g_top_idx[src];                  // rows
        out[1024 + dst] = (float)t;                               // cols
        out[2048 + dst] = (g_top_val[src] >= 0.0f) ? 1.0f : 0.0f; // valid
    }
}

// ---------------------------------------------------------------------------
extern "C" void kernel_launch(void* const* d_in, const int* in_sizes, int n_in,
                              void* d_out, int out_size)
{
    const float *th, *xy, *di, *po, *ne, *io, *tg, *W1, *b1, *W2, *b2, *W3, *b3;

    if (n_in >= 13 && in_sizes[0] == 6 * 64) {
        // Alphabetical metadata order
        W1 = (const float*)d_in[0];  W2 = (const float*)d_in[1];
        W3 = (const float*)d_in[2];  b1 = (const float*)d_in[3];
        b2 = (const float*)d_in[4];  b3 = (const float*)d_in[5];
        di = (const float*)d_in[6];  io = (const float*)d_in[7];
        ne = (const float*)d_in[8];  po = (const float*)d_in[9];
        xy = (const float*)d_in[10]; tg = (const float*)d_in[11];
        th = (const float*)d_in[12];
    } else {
        // Insertion (dict) order
        th = (const float*)d_in[0];  xy = (const float*)d_in[1];
        di = (const float*)d_in[2];  po = (const float*)d_in[3];
        ne = (const float*)d_in[4];  io = (const float*)d_in[5];
        tg = (const float*)d_in[6];  W1 = (const float*)d_in[7];
        b1 = (const float*)d_in[8];  W2 = (const float*)d_in[9];
        b2 = (const float*)d_in[10]; W3 = (const float*)d_in[11];
        b3 = (const float*)d_in[12];
    }

    score_mma_kernel<<<4096, 128>>>(th, xy, di, po, ne, io,
                                    W1, b1, W2, b2, W3, b3);
    topk16_kernel<<<N_TGT, 256>>>();
    rescore_kernel<<<N_TGT, 32>>>(th, xy, di, po, ne, io,
                                  W1, b1, W2, b2, W3, b3);
    assemble_kernel<<<1, N_TGT>>>(tg, (float*)d_out);
}

// round 14
// speedup vs baseline: 3.6005x; 1.1093x over previous
#include <cuda_runtime.h>
#include <cuda_bf16.h>

#define N_PROP 65536
#define N_TGT  128
#define KTOP   8
#define KCAND  16

typedef unsigned int u32;

// Scratch (static __device__ — no allocations allowed)
__device__ float g_scoresT[(size_t)N_TGT * N_PROP];   // [T][N] approx keys
__device__ int   g_cand_idx[N_TGT * KCAND];
__device__ float g_top_val[N_TGT * KTOP];
__device__ int   g_top_idx[N_TGT * KTOP];

// pack two f32 -> bf16x2 (lo = second arg)
static __device__ __forceinline__ u32 bfpair(float hi, float lo) {
    u32 d;
    asm("cvt.rn.bf16x2.f32 %0, %1, %2;" : "=r"(d) : "f"(hi), "f"(lo));
    return d;
}

static __device__ __forceinline__ void mma_k8(float c[4], u32 a0, u32 a1, u32 b0) {
    asm volatile(
        "mma.sync.aligned.m16n8k8.row.col.f32.bf16.bf16.f32 "
        "{%0,%1,%2,%3}, {%4,%5}, {%6}, {%0,%1,%2,%3};"
        : "+f"(c[0]), "+f"(c[1]), "+f"(c[2]), "+f"(c[3])
        : "r"(a0), "r"(a1), "r"(b0));
}
static __device__ __forceinline__ void mma_k16(float c[4], const u32 a[4],
                                               u32 b0, u32 b1) {
    asm volatile(
        "mma.sync.aligned.m16n8k16.row.col.f32.bf16.bf16.f32 "
        "{%0,%1,%2,%3}, {%4,%5,%6,%7}, {%8,%9}, {%0,%1,%2,%3};"
        : "+f"(c[0]), "+f"(c[1]), "+f"(c[2]), "+f"(c[3])
        : "r"(a[0]), "r"(a[1]), "r"(a[2]), "r"(a[3]), "r"(b0), "r"(b1));
}

// ---------------------------------------------------------------------------
// Phase A: warp-level HMMA approximate scoring, 2 tiles (32 rows) per warp
// iteration for ILP. Rows = (n,t) pairs, row = n*128 + t.
//   L1: H1[16,64] = [feats|1][16,8] @ [W1|b1]  -> 8x mma.m16n8k8 (bf16)
//       -> immediately compressed to bf16 A-frags (16 u32) per tile
//   L2: H2[16,32] = relu(H1) @ W2 (+b2 via C-init) -> 16x mma.m16n8k16
//   L3: logit = relu(H2) . W3 + b3              -> scalar + 2 quad shuffles
// key = logit>=0 ? logit : -1  (approx; exact re-ranking in phase B)
// ---------------------------------------------------------------------------
__global__ __launch_bounds__(128) void score_mma_kernel(
    const float* __restrict__ th, const float* __restrict__ xy,
    const float* __restrict__ di, const float* __restrict__ po,
    const float* __restrict__ ne, const float* __restrict__ io,
    const float* __restrict__ W1, const float* __restrict__ b1,
    const float* __restrict__ W2, const float* __restrict__ b2,
    const float* __restrict__ W3, const float* __restrict__ b3)
{
    const int lane = threadIdx.x & 31;
    const int grp  = lane >> 2;       // 0..7  (row within tile; +8 for upper)
    const int qid  = lane & 3;        // 0..3  (K/N column group)

    const int warps_per_blk = blockDim.x >> 5;
    const int gwarp  = blockIdx.x * warps_per_blk + (threadIdx.x >> 5);
    const int nwarp  = gridDim.x * warps_per_blk;
    const int npairs = (N_PROP * N_TGT) / 32;   // 2 tiles per iteration

    // ---- W1 B-fragments (k8): b[jt] covers hidden units 8*jt..8*jt+7 ----
    u32 bw1[8];
    {
        const int k0 = 2 * qid;
        #pragma unroll
        for (int jt = 0; jt < 8; jt++) {
            const int n = 8 * jt + grp;
            float lo = (k0 == 6) ? b1[n] : W1[k0 * 64 + n];
            float hi = (k0 + 1 == 7) ? 0.0f : W1[(k0 + 1) * 64 + n];
            bw1[jt] = bfpair(hi, lo);
        }
    }

    // ---- W2 B-fragments (k16): [kt][nt] ----
    u32 bw2[4][4][2];
    {
        #pragma unroll
        for (int kt = 0; kt < 4; kt++) {
            const int k0 = 16 * kt + 2 * qid;
            #pragma unroll
            for (int nt = 0; nt < 4; nt++) {
                const int n = 8 * nt + grp;
                bw2[kt][nt][0] = bfpair(W2[(k0 + 1) * 32 + n], W2[k0 * 32 + n]);
                bw2[kt][nt][1] = bfpair(W2[(k0 + 9) * 32 + n], W2[(k0 + 8) * 32 + n]);
            }
        }
    }

    // ---- L3 per-lane constants: cols 8*nt + 2*qid + e ----
    float w3v[4][2], b2v[4][2];
    #pragma unroll
    for (int nt = 0; nt < 4; nt++) {
        #pragma unroll
        for (int e = 0; e < 2; e++) {
            const int c = 8 * nt + 2 * qid + e;
            w3v[nt][e] = W3[c];
            b2v[nt][e] = b2[c];
        }
    }
    const float b3v = b3[0];

    // per-lane feature sources: features 2*qid and 2*qid+1
    const float* pA = (qid == 0) ? th : (qid == 1) ? di : ne;   // qid3: dummy
    const float* pB = (qid == 0) ? xy : (qid == 1) ? po : io;
    const float capA = (qid == 0) ? 180.0f : (qid == 1) ? 800.0f : 0.0f;
    const float capB = (qid == 0) ? 800.0f : 0.0f;
    const float invA = (qid == 0) ? (1.0f / 180.0f) : (1.0f / 800.0f);
    const float invB = 1.0f / 800.0f;

    for (int pair = gwarp; pair < npairs; pair += nwarp) {
        const int row0 = pair * 32 + grp;     // tile0: rows row0, row0+8
        const int row1 = row0 + 16;           // tile1: rows row1, row1+8

        // ---- A-fragments for L1 (k8) for both tiles ----
        u32 a0, a1, c0, c1;
        if (qid == 3) {
            a0 = 0x00003F80u; a1 = 0x00003F80u;   // (col6=1.0 bias, col7=0)
            c0 = 0x00003F80u; c1 = 0x00003F80u;
        } else {
            float vA0 = pA[row0],      vB0 = pB[row0];
            float vA8 = pA[row0 + 8],  vB8 = pB[row0 + 8];
            float vC0 = pA[row1],      vD0 = pB[row1];
            float vC8 = pA[row1 + 8],  vD8 = pB[row1 + 8];
            float fA0 = (capA > 0.0f) ? 1.0f - fminf(vA0, capA) * invA : vA0;
            float fA8 = (capA > 0.0f) ? 1.0f - fminf(vA8, capA) * invA : vA8;
            float fC0 = (capA > 0.0f) ? 1.0f - fminf(vC0, capA) * invA : vC0;
            float fC8 = (capA > 0.0f) ? 1.0f - fminf(vC8, capA) * invA : vC8;
            float fB0 = (capB > 0.0f) ? 1.0f - fminf(vB0, capB) * invB : vB0;
            float fB8 = (capB > 0.0f) ? 1.0f - fminf(vB8, capB) * invB : vB8;
            float fD0 = (capB > 0.0f) ? 1.0f - fminf(vD0, capB) * invB : vD0;
            float fD8 = (capB > 0.0f) ? 1.0f - fminf(vD8, capB) * invB : vD8;
            a0 = bfpair(fB0, fA0);
            a1 = bfpair(fB8, fA8);
            c0 = bfpair(fD0, fC0);
            c1 = bfpair(fD8, fC8);
        }

        // ---- L1 tile0 -> compressed A-frags aF0[kt][4] ----
        u32 aF0[4][4], aF1[4][4];
        {
            float h1[8][4];
            #pragma unroll
            for (int jt = 0; jt < 8; jt++) {
                h1[jt][0] = 0.0f; h1[jt][1] = 0.0f; h1[jt][2] = 0.0f; h1[jt][3] = 0.0f;
                mma_k8(h1[jt], a0, a1, bw1[jt]);
            }
            #pragma unroll
            for (int kt = 0; kt < 4; kt++) {
                aF0[kt][0] = bfpair(fmaxf(h1[2*kt][1], 0.0f),   fmaxf(h1[2*kt][0], 0.0f));
                aF0[kt][1] = bfpair(fmaxf(h1[2*kt][3], 0.0f),   fmaxf(h1[2*kt][2], 0.0f));
                aF0[kt][2] = bfpair(fmaxf(h1[2*kt+1][1], 0.0f), fmaxf(h1[2*kt+1][0], 0.0f));
                aF0[kt][3] = bfpair(fmaxf(h1[2*kt+1][3], 0.0f), fmaxf(h1[2*kt+1][2], 0.0f));
            }
        }
        // ---- L1 tile1 ----
        {
            float h1[8][4];
            #pragma unroll
            for (int jt = 0; jt < 8; jt++) {
                h1[jt][0] = 0.0f; h1[jt][1] = 0.0f; h1[jt][2] = 0.0f; h1[jt][3] = 0.0f;
                mma_k8(h1[jt], c0, c1, bw1[jt]);
            }
            #pragma unroll
            for (int kt = 0; kt < 4; kt++) {
                aF1[kt][0] = bfpair(fmaxf(h1[2*kt][1], 0.0f),   fmaxf(h1[2*kt][0], 0.0f));
                aF1[kt][1] = bfpair(fmaxf(h1[2*kt][3], 0.0f),   fmaxf(h1[2*kt][2], 0.0f));
                aF1[kt][2] = bfpair(fmaxf(h1[2*kt+1][1], 0.0f), fmaxf(h1[2*kt+1][0], 0.0f));
                aF1[kt][3] = bfpair(fmaxf(h1[2*kt+1][3], 0.0f), fmaxf(h1[2*kt+1][2], 0.0f));
            }
        }

        // ---- L2: two independent accumulation chains, b2 folded into C ----
        float h2a[4][4], h2b[4][4];
        #pragma unroll
        for (int nt = 0; nt < 4; nt++) {
            h2a[nt][0] = b2v[nt][0]; h2a[nt][1] = b2v[nt][1];
            h2a[nt][2] = b2v[nt][0]; h2a[nt][3] = b2v[nt][1];
            h2b[nt][0] = b2v[nt][0]; h2b[nt][1] = b2v[nt][1];
            h2b[nt][2] = b2v[nt][0]; h2b[nt][3] = b2v[nt][1];
        }
        #pragma unroll
        for (int kt = 0; kt < 4; kt++) {
            #pragma unroll
            for (int nt = 0; nt < 4; nt++) {
                mma_k16(h2a[nt], aF0[kt], bw2[kt][nt][0], bw2[kt][nt][1]);
                mma_k16(h2b[nt], aF1[kt], bw2[kt][nt][0], bw2[kt][nt][1]);
            }
        }

        // ---- L3: relu(H2) . W3, quad reduction; two tiles interleaved ----
        float p0 = 0.0f, p8 = 0.0f, q0 = 0.0f, q8 = 0.0f;
        #pragma unroll
        for (int nt = 0; nt < 4; nt++) {
            #pragma unroll
            for (int e = 0; e < 2; e++) {
                p0 = fmaf(fmaxf(h2a[nt][e],     0.0f), w3v[nt][e], p0);
                p8 = fmaf(fmaxf(h2a[nt][2 + e], 0.0f), w3v[nt][e], p8);
                q0 = fmaf(fmaxf(h2b[nt][e],     0.0f), w3v[nt][e], q0);
                q8 = fmaf(fmaxf(h2b[nt][2 + e], 0.0f), w3v[nt][e], q8);
            }
        }
        p0 += __shfl_xor_sync(0xFFFFFFFFu, p0, 1);
        p8 += __shfl_xor_sync(0xFFFFFFFFu, p8, 1);
        q0 += __shfl_xor_sync(0xFFFFFFFFu, q0, 1);
        q8 += __shfl_xor_sync(0xFFFFFFFFu, q8, 1);
        p0 += __shfl_xor_sync(0xFFFFFFFFu, p0, 2);
        p8 += __shfl_xor_sync(0xFFFFFFFFu, p8, 2);
        q0 += __shfl_xor_sync(0xFFFFFFFFu, q0, 2);
        q8 += __shfl_xor_sync(0xFFFFFFFFu, q8, 2);

        if (qid == 0) {
            const float l0 = p0 + b3v, l8 = p8 + b3v;
            const float m0 = q0 + b3v, m8 = q8 + b3v;
            const int r0 = row0, r8 = row0 + 8;
            const int s0 = row1, s8 = row1 + 8;
            g_scoresT[(size_t)(r0 & 127) * N_PROP + (r0 >> 7)] = (l0 >= 0.0f) ? l0 : -1.0f;
            g_scoresT[(size_t)(r8 & 127) * N_PROP + (r8 >> 7)] = (l8 >= 0.0f) ? l8 : -1.0f;
            g_scoresT[(size_t)(s0 & 127) * N_PROP + (s0 >> 7)] = (m0 >= 0.0f) ? m0 : -1.0f;
            g_scoresT[(size_t)(s8 & 127) * N_PROP + (s8 >> 7)] = (m8 >= 0.0f) ? m8 : -1.0f;
        }
    }
}

// ---------------------------------------------------------------------------
// Phase A topk: per-target top-16 candidates (ties -> lowest index).
// ---------------------------------------------------------------------------
__global__ __launch_bounds__(256) void topk16_kernel()
{
    __shared__ float sval[256 * KCAND];
    __shared__ int   sidx[256 * KCAND];

    const int t   = blockIdx.x;
    const int tid = threadIdx.x;
    const float4* __restrict__ col4 = (const float4*)(g_scoresT + (size_t)t * N_PROP);

    float val[KCAND];
    int   idx[KCAND];
    #pragma unroll
    for (int k = 0; k < KCAND; k++) { val[k] = -3.4e38f; idx[k] = 0x7fffffff; }

    for (int q = tid; q < N_PROP / 4; q += 256) {
        const float4 v4 = col4[q];
        const int nb = q * 4;
        float vv[4] = {v4.x, v4.y, v4.z, v4.w};
        #pragma unroll
        for (int u = 0; u < 4; u++) {
            const float v = vv[u];
            if (v > val[KCAND - 1]) {
                val[KCAND - 1] = v; idx[KCAND - 1] = nb + u;
                #pragma unroll
                for (int p = KCAND - 1; p > 0; p--) {
                    if (val[p] > val[p - 1]) {
                        float tv = val[p]; val[p] = val[p - 1]; val[p - 1] = tv;
                        int   ti = idx[p]; idx[p] = idx[p - 1]; idx[p - 1] = ti;
                    }
                }
            }
        }
    }

    #pragma unroll
    for (int k = 0; k < KCAND; k++) { sval[tid * KCAND + k] = val[k]; sidx[tid * KCAND + k] = idx[k]; }
    __syncthreads();

    for (int s = 128; s > 0; s >>= 1) {
        float mv[KCAND]; int mi[KCAND];
        if (tid < s) {
            const float* av = &sval[tid * KCAND];
            const int*   ai = &sidx[tid * KCAND];
            const float* bv = &sval[(tid + s) * KCAND];
            const int*   bi = &sidx[(tid + s) * KCAND];
            int i = 0, j = 0;
            #pragma unroll
            for (int k = 0; k < KCAND; k++) {
                const float va = av[i], vb = bv[j];
                const int   ia = ai[i], ib = bi[j];
                const bool take_a = (va > vb) || (va == vb && ia < ib);
                if (take_a) { mv[k] = va; mi[k] = ia; i++; }
                else        { mv[k] = vb; mi[k] = ib; j++; }
            }
            #pragma unroll
            for (int k = 0; k < KCAND; k++) { sval[tid * KCAND + k] = mv[k]; sidx[tid * KCAND + k] = mi[k]; }
        }
        __syncthreads();
    }

    if (tid == 0) {
        #pragma unroll
        for (int k = 0; k < KCAND; k++)
            g_cand_idx[t * KCAND + k] = sidx[k];
    }
}

// ---------------------------------------------------------------------------
// Phase B: exact fp32 rescoring of the 16 candidates per target, exact top-8.
// ---------------------------------------------------------------------------
__global__ __launch_bounds__(32) void rescore_kernel(
    const float* __restrict__ th, const float* __restrict__ xy,
    const float* __restrict__ di, const float* __restrict__ po,
    const float* __restrict__ ne, const float* __restrict__ io,
    const float* __restrict__ W1, const float* __restrict__ b1,
    const float* __restrict__ W2, const float* __restrict__ b2,
    const float* __restrict__ W3, const float* __restrict__ b3)
{
    __shared__ float skv[KCAND];
    __shared__ int   ski[KCAND];

    const int t   = blockIdx.x;
    const int tid = threadIdx.x;

    if (tid < KCAND) {
        const int n   = g_cand_idx[t * KCAND + tid];
        const int off = n * N_TGT + t;
        float f[6];
        f[0] = 1.0f - fminf(th[off], 180.0f) * (1.0f / 180.0f);
        f[1] = 1.0f - fminf(xy[off], 800.0f) * (1.0f / 800.0f);
        f[2] = 1.0f - fminf(di[off], 800.0f) * (1.0f / 800.0f);
        f[3] = po[off];
        f[4] = ne[off];
        f[5] = io[off];

        float h2[32];
        #pragma unroll
        for (int j = 0; j < 32; j++) h2[j] = b2[j];

        for (int i = 0; i < 64; i++) {
            float h = b1[i];
            #pragma unroll
            for (int k = 0; k < 6; k++) h = fmaf(f[k], W1[k * 64 + i], h);
            h = fmaxf(h, 0.0f);
            #pragma unroll
            for (int j = 0; j < 32; j++) h2[j] = fmaf(h, W2[i * 32 + j], h2[j]);
        }
        float acc = b3[0];
        #pragma unroll
        for (int j = 0; j < 32; j++)
            acc = fmaf(fmaxf(h2[j], 0.0f), W3[j], acc);

        skv[tid] = (acc >= 0.0f) ? acc : -1.0f;
        ski[tid] = n;
    }
    __syncthreads();

    if (tid == 0) {
        bool used[KCAND];
        #pragma unroll
        for (int k = 0; k < KCAND; k++) used[k] = false;
        for (int k = 0; k < KTOP; k++) {
            int best = -1;
            float bv = -3.4e38f; int bi = 0x7fffffff;
            for (int c = 0; c < KCAND; c++) {
                if (used[c]) continue;
                const float v = skv[c]; const int n = ski[c];
                if (v > bv || (v == bv && n < bi)) { bv = v; bi = n; best = c; }
            }
            used[best] = true;
            g_top_val[t * KTOP + k] = bv;
            g_top_idx[t * KTOP + k] = bi;
        }
    }
}

// ---------------------------------------------------------------------------
// Final: stable descending rank of targets[:,1], scatter output as float32.
// out = [rows(1024) | cols(1024) | valid(1024)].
// ---------------------------------------------------------------------------
__global__ __launch_bounds__(N_TGT) void assemble_kernel(
    const float* __restrict__ targets, float* __restrict__ out)
{
    __shared__ float key[N_TGT];
    const int t = threadIdx.x;
    key[t] = targets[t * 4 + 1];
    __syncthreads();

    const float kt = key[t];
    int r = 0;
    #pragma unroll 8
    for (int j = 0; j < N_TGT; j++) {
        const float kj = key[j];
        r += (kj > kt) || (kj == kt && j < t);   // stable descending
    }

    #pragma unroll
    for (int k = 0; k < KTOP; k++) {
        const int src = t * KTOP + k;
        const int dst = r * KTOP + k;
        out[dst]        = (float)g_top_idx[src];                  // rows
        out[1024 + dst] = (float)t;                               // cols
        out[2048 + dst] = (g_top_val[src] >= 0.0f) ? 1.0f : 0.0f; // valid
    }
}

// ---------------------------------------------------------------------------
extern "C" void kernel_launch(void* const* d_in, const int* in_sizes, int n_in,
                              void* d_out, int out_size)
{
    const float *th, *xy, *di, *po, *ne, *io, *tg, *W1, *b1, *W2, *b2, *W3, *b3;

    if (n_in >= 13 && in_sizes[0] == 6 * 64) {
        // Alphabetical metadata order
        W1 = (const float*)d_in[0];  W2 = (const float*)d_in[1];
        W3 = (const float*)d_in[2];  b1 = (const float*)d_in[3];
        b2 = (const float*)d_in[4];  b3 = (const float*)d_in[5];
        di = (const float*)d_in[6];  io = (const float*)d_in[7];
        ne = (const float*)d_in[8];  po = (const float*)d_in[9];
        xy = (const float*)d_in[10]; tg = (const float*)d_in[11];
        th = (const float*)d_in[12];
    } else {
        // Insertion (dict) order
        th = (const float*)d_in[0];  xy = (const float*)d_in[1];
        di = (const float*)d_in[2];  po = (const float*)d_in[3];
        ne = (const float*)d_in[4];  io = (const float*)d_in[5];
        tg = (const float*)d_in[6];  W1 = (const float*)d_in[7];
        b1 = (const float*)d_in[8];  W2 = (const float*)d_in[9];
        b2 = (const float*)d_in[10]; W3 = (const float*)d_in[11];
        b3 = (const float*)d_in[12];
    }

    score_mma_kernel<<<4096, 128>>>(th, xy, di, po, ne, io,
                                    W1, b1, W2, b2, W3, b3);
    topk16_kernel<<<N_TGT, 256>>>();
    rescore_kernel<<<N_TGT, 32>>>(th, xy, di, po, ne, io,
                                  W1, b1, W2, b2, W3, b3);
    assemble_kernel<<<1, N_TGT>>>(tg, (float*)d_out);
}